// round 14
// baseline (speedup 1.0000x reference)
#include <cuda_runtime.h>

#define N_NODES 50000
#define N_EDGES 1200000
#define N_REL   45
#define IN_C    64
#define HID_C   32
#define OUT_C   16

#define SCAT_EPB 2048   // edges per scatter block
#define WT_PAD   36     // Wt row stride (144B: 16B-aligned)
#define XT_STR   68     // xt row stride in floats (64 edges + 4 pad; 4*68%32==16)

typedef unsigned long long u64;

#define RED2(ptr, v0, v1) \
    asm volatile("red.global.add.v2.f32 [%0], {%1, %2};" \
                 :: "l"(ptr), "f"(v0), "f"(v1) : "memory")
#define FMA2(acc, a, b) \
    asm("fma.rn.f32x2 %0, %1, %2, %0;" : "+l"(acc) : "l"(a), "l"(b))
#define PACK2(out, lo, hi) \
    asm("mov.b64 %0, {%1, %2};" : "=l"(out) : "f"(lo), "f"(hi))
#define UNPACK2(lo, hi, in) \
    asm("mov.b64 {%0, %1}, %2;" : "=f"(lo), "=f"(hi) : "l"(in))

// Scratch (device globals: no allocation allowed in kernel_launch)
__device__ int   g_cnt[N_REL * N_NODES];
__device__ int   g_hist[N_REL];
__device__ int   g_off[N_REL + 1];
__device__ int   g_cursor[N_REL];
__device__ unsigned g_done;
__device__ int   g_rel[N_EDGES];
__device__ int   gs_src[N_EDGES];
__device__ int   gs_dst[N_EDGES];
__device__ float gs_w[N_EDGES];
__device__ float g_h1[N_NODES * HID_C];
__device__ float g_hr[N_NODES * HID_C];

// ---------------------------------------------------------------------------
__global__ void zero_kernel() {
    int i = blockIdx.x * blockDim.x + threadIdx.x;
    int stride = gridDim.x * blockDim.x;
    for (; i < N_REL * N_NODES; i += stride) g_cnt[i] = 0;
    int j = blockIdx.x * blockDim.x + threadIdx.x;
    for (; j < N_NODES * HID_C; j += stride) g_h1[j] = 0.0f;
    if (blockIdx.x == 0 && threadIdx.x < N_REL) g_hist[threadIdx.x] = 0;
    if (blockIdx.x == 0 && threadIdx.x == 0) g_done = 0;
}

__global__ void count_kernel(const int* __restrict__ edge_index,
                             const int* __restrict__ edge_type) {
    __shared__ int sh[N_REL];
    if (threadIdx.x < N_REL) sh[threadIdx.x] = 0;
    __syncthreads();
    int e = blockIdx.x * blockDim.x + threadIdx.x;
    if (e < N_EDGES) {
        int dst = edge_index[N_EDGES + e];
        int rel = edge_type[e];
        g_rel[e] = rel;
        atomicAdd(&g_cnt[rel * N_NODES + dst], 1);
        atomicAdd(&sh[rel], 1);
    }
    __syncthreads();
    if (threadIdx.x < N_REL) {
        atomicAdd(&g_hist[threadIdx.x], sh[threadIdx.x]);
        __threadfence();
    }
    __syncthreads();
    if (threadIdx.x == 0) {
        unsigned t = atomicInc(&g_done, 0xffffffffu);
        if (t == gridDim.x - 1) {
            int acc = 0;
            for (int r = 0; r < N_REL; r++) {
                g_off[r] = acc;
                g_cursor[r] = acc;
                acc += g_hist[r];
            }
            g_off[N_REL] = acc;
        }
    }
}

__global__ __launch_bounds__(256)
void scatter_kernel(const int* __restrict__ edge_index) {
    __shared__ int sh_cnt[N_REL];
    __shared__ int sh_base[N_REL];
    const int blockStart = blockIdx.x * SCAT_EPB;

    if (threadIdx.x < N_REL) sh_cnt[threadIdx.x] = 0;
    __syncthreads();
    for (int i = threadIdx.x; i < SCAT_EPB; i += blockDim.x) {
        int e = blockStart + i;
        if (e < N_EDGES) atomicAdd(&sh_cnt[g_rel[e]], 1);
    }
    __syncthreads();
    if (threadIdx.x < N_REL) {
        sh_base[threadIdx.x] = atomicAdd(&g_cursor[threadIdx.x], sh_cnt[threadIdx.x]);
        sh_cnt[threadIdx.x] = 0;
    }
    __syncthreads();
    for (int i = threadIdx.x; i < SCAT_EPB; i += blockDim.x) {
        int e = blockStart + i;
        if (e >= N_EDGES) continue;
        int rel = g_rel[e];
        int pos = sh_base[rel] + atomicAdd(&sh_cnt[rel], 1);
        int src = edge_index[e];
        int dst = edge_index[N_EDGES + e];
        int c   = g_cnt[rel * N_NODES + dst];
        gs_src[pos] = src;
        gs_dst[pos] = dst;
        gs_w[pos]   = 1.0f / (float)(c > 0 ? c : 1);
    }
}

// ---------------------------------------------------------------------------
// Layer-1 messages: warp tile = 64 edges x 32 channels; thread = 8 edges x
// 8 channels, f32x2 packed FMA. W-pair LDS amortized over 2x edges vs r13
// (per kk/thread: 2 x-LDS + 2 W-LDS + 32 FMA2). x staged transposed in 16-k
// chunks; k-split (part*4) makes paired STS bank-disjoint (4*68 % 32 == 16).
__global__ __launch_bounds__(256, 2)
void msg1_kernel(const float* __restrict__ x, const float* __restrict__ W1) {
    __shared__ float Wt[IN_C][WT_PAD];         //  9216B
    __shared__ float xt[8][16][XT_STR];        // 34816B  (total 44032 < 48K)

    const int tid  = threadIdx.x;
    const int lane = tid & 31;
    const int warp = tid >> 5;     // 0..7
    const int r    = blockIdx.x;

    const float* Wr = W1 + r * IN_C * HID_C;
    for (int i = tid; i < IN_C * HID_C; i += 256)
        Wt[i >> 5][i & 31] = Wr[i];
    __syncthreads();

    const int segStart = g_off[r];
    const int segEnd   = g_off[r + 1];
    const int wg = blockIdx.y * 8 + warp;
    const int nw = gridDim.y * 8;

    const int e0   = (lane & 7) * 8;   // this thread's 8 edges in the tile
    const int cg   = lane >> 3;        // channel group (8 ch)
    const int part = lane & 1;
    const int srow = lane >> 1;        // 0..15 staging row base

    for (int base = segStart + wg * 64; base < segEnd; base += nw * 64) {
        int n = segEnd - base; if (n > 64) n = 64;
        int sA, dA = 0, sB, dB = 0; float wA_ = 0.0f, wB_ = 0.0f;
        {
            int iA = base + lane, iB = base + 32 + lane;
            if (lane < n)      { sA = gs_src[iA]; dA = gs_dst[iA]; wA_ = gs_w[iA]; }
            else               { sA = gs_src[segStart]; }
            if (lane + 32 < n) { sB = gs_src[iB]; dB = gs_dst[iB]; wB_ = gs_w[iB]; }
            else               { sB = gs_src[segStart]; }
        }

        u64 accp[8][4];
#pragma unroll
        for (int i = 0; i < 8; i++)
#pragma unroll
            for (int p = 0; p < 4; p++) accp[i][p] = 0ull;

#pragma unroll
        for (int chunk = 0; chunk < 4; chunk++) {    // 16 k per chunk
            // stage 64 rows x 16 k (transposed), 2 lanes per row
#pragma unroll
            for (int pass = 0; pass < 4; pass++) {
                int row = srow + pass * 16;          // 0..63 (uniform per pass)
                int s = (pass < 2) ? __shfl_sync(0xffffffffu, sA, row)
                                   : __shfl_sync(0xffffffffu, sB, row - 32);
                const float4* src4 =
                    (const float4*)(x + (size_t)s * IN_C) + chunk * 4 + part;
                float4 v0 = src4[0];   // k = chunk*16 + part*4 + j
                float4 v1 = src4[2];   // k = chunk*16 + 8 + part*4 + j
                int kb = part * 4;
                xt[warp][kb + 0][row] = v0.x;
                xt[warp][kb + 1][row] = v0.y;
                xt[warp][kb + 2][row] = v0.z;
                xt[warp][kb + 3][row] = v0.w;
                xt[warp][kb + 8][row] = v1.x;
                xt[warp][kb + 9][row] = v1.y;
                xt[warp][kb + 10][row] = v1.z;
                xt[warp][kb + 11][row] = v1.w;
            }
            __syncwarp();

            // 16 k-steps: 2 x-LDS.128 + 2 W-LDS.128 + 8 packs + 32 FMA2
#pragma unroll
            for (int kk = 0; kk < 16; kk++) {
                float4 xa = *(const float4*)&xt[warp][kk][e0];
                float4 xb = *(const float4*)&xt[warp][kk][e0 + 4];
                const ulonglong2* wrow =
                    (const ulonglong2*)&Wt[chunk * 16 + kk][cg * 8];
                ulonglong2 wP = wrow[0];
                ulonglong2 wQ = wrow[1];
                u64 xx[8];
                PACK2(xx[0], xa.x, xa.x); PACK2(xx[1], xa.y, xa.y);
                PACK2(xx[2], xa.z, xa.z); PACK2(xx[3], xa.w, xa.w);
                PACK2(xx[4], xb.x, xb.x); PACK2(xx[5], xb.y, xb.y);
                PACK2(xx[6], xb.z, xb.z); PACK2(xx[7], xb.w, xb.w);
#pragma unroll
                for (int i = 0; i < 8; i++) {
                    FMA2(accp[i][0], xx[i], wP.x);
                    FMA2(accp[i][1], xx[i], wP.y);
                    FMA2(accp[i][2], xx[i], wQ.x);
                    FMA2(accp[i][3], xx[i], wQ.y);
                }
            }
            __syncwarp();   // before next chunk overwrites xt
        }

        // epilogue: unpack, scale by 1/cnt, vector RED scatter
#pragma unroll
        for (int i = 0; i < 8; i++) {
            int e = e0 + i;
            int dLo = __shfl_sync(0xffffffffu, dA, e & 31);
            int dHi = __shfl_sync(0xffffffffu, dB, e & 31);
            float wLo = __shfl_sync(0xffffffffu, wA_, e & 31);
            float wHi = __shfl_sync(0xffffffffu, wB_, e & 31);
            int   d  = (e < 32) ? dLo : dHi;
            float we = (e < 32) ? wLo : wHi;
            float* p = &g_h1[d * HID_C + cg * 8];
            float v0, v1;
            UNPACK2(v0, v1, accp[i][0]); RED2(p + 0, v0 * we, v1 * we);
            UNPACK2(v0, v1, accp[i][1]); RED2(p + 2, v0 * we, v1 * we);
            UNPACK2(v0, v1, accp[i][2]); RED2(p + 4, v0 * we, v1 * we);
            UNPACK2(v0, v1, accp[i][3]); RED2(p + 6, v0 * we, v1 * we);
        }
    }
}

// ---------------------------------------------------------------------------
__global__ void root1_relu_kernel(const float* __restrict__ x,
                                  const float* __restrict__ root,
                                  const float* __restrict__ b) {
    int t = blockIdx.x * blockDim.x + threadIdx.x;
    if (t >= N_NODES * HID_C) return;
    int n = t >> 5;
    int c = t & 31;
    float acc = b[c] + g_h1[t];
    const float4* xr = (const float4*)(x + n * IN_C);
#pragma unroll
    for (int i4 = 0; i4 < IN_C / 4; i4++) {
        float4 xv = xr[i4];
        acc += xv.x * root[(i4 * 4 + 0) * HID_C + c];
        acc += xv.y * root[(i4 * 4 + 1) * HID_C + c];
        acc += xv.z * root[(i4 * 4 + 2) * HID_C + c];
        acc += xv.w * root[(i4 * 4 + 3) * HID_C + c];
    }
    g_hr[t] = fmaxf(acc, 0.0f);
}

__global__ void root2_kernel(const float* __restrict__ root,
                             const float* __restrict__ b,
                             float* __restrict__ out) {
    int t = blockIdx.x * blockDim.x + threadIdx.x;
    if (t >= N_NODES * OUT_C) return;
    int n = t >> 4;
    int c = t & 15;
    float acc = b[c];
    const float4* hr = (const float4*)(g_hr + n * HID_C);
#pragma unroll
    for (int i4 = 0; i4 < HID_C / 4; i4++) {
        float4 hv = hr[i4];
        acc += hv.x * root[(i4 * 4 + 0) * OUT_C + c];
        acc += hv.y * root[(i4 * 4 + 1) * OUT_C + c];
        acc += hv.z * root[(i4 * 4 + 2) * OUT_C + c];
        acc += hv.w * root[(i4 * 4 + 3) * OUT_C + c];
    }
    out[t] = acc;
}

// Layer-2 messages over g_hr (already ReLU'd). Half-warp per edge.
__global__ __launch_bounds__(512, 1)
void msg2_kernel(const float* __restrict__ W2, float* __restrict__ out) {
    const int r    = blockIdx.x;
    const int lane = threadIdx.x & 31;
    const int warp = threadIdx.x >> 5;
    const int c    = lane & 15;
    const int half = lane >> 4;

    float Wreg[HID_C];
    const float* Wr = W2 + r * HID_C * OUT_C;
#pragma unroll
    for (int k = 0; k < HID_C; k++) Wreg[k] = Wr[k * OUT_C + c];

    const int segStart = g_off[r];
    const int segEnd   = g_off[r + 1];
    const int wg = blockIdx.y * 16 + warp;
    const int nw = gridDim.y * 16;

    for (int base = segStart + wg * 32; base < segEnd; base += nw * 32) {
        int n = segEnd - base; if (n > 32) n = 32;
        int s32 = 0, d32 = 0; float w32 = 0.0f;
        if (lane < n) {
            s32 = gs_src[base + lane];
            d32 = gs_dst[base + lane];
            w32 = gs_w[base + lane];
        }
        int nPairs = (n + 1) >> 1;
#pragma unroll 2
        for (int jj = 0; jj < nPairs; jj++) {
            int ej = jj * 2 + half;
            bool act = ej < n;
            int sel = act ? ej : 0;
            int s = __shfl_sync(0xffffffffu, s32, sel);
            int d = __shfl_sync(0xffffffffu, d32, sel);
            float wj = __shfl_sync(0xffffffffu, w32, sel);
            const float4* hr = (const float4*)(g_hr + s * HID_C);
            float a0 = 0.0f, a1 = 0.0f;
#pragma unroll
            for (int k4 = 0; k4 < HID_C / 8; k4++) {
                float4 h0 = hr[k4 * 2 + 0];
                float4 h1 = hr[k4 * 2 + 1];
                a0 += h0.x * Wreg[k4 * 8 + 0]; a0 += h0.y * Wreg[k4 * 8 + 1];
                a0 += h0.z * Wreg[k4 * 8 + 2]; a0 += h0.w * Wreg[k4 * 8 + 3];
                a1 += h1.x * Wreg[k4 * 8 + 4]; a1 += h1.y * Wreg[k4 * 8 + 5];
                a1 += h1.z * Wreg[k4 * 8 + 6]; a1 += h1.w * Wreg[k4 * 8 + 7];
            }
            if (act) atomicAdd(&out[d * OUT_C + c], (a0 + a1) * wj);
        }
    }
}

// ---------------------------------------------------------------------------
extern "C" void kernel_launch(void* const* d_in, const int* in_sizes, int n_in,
                              void* d_out, int out_size) {
    const float* x          = (const float*)d_in[0];
    const int*   edge_index = (const int*)d_in[1];
    const int*   edge_type  = (const int*)d_in[2];
    const float* W1         = (const float*)d_in[3];
    const float* root1      = (const float*)d_in[4];
    const float* b1         = (const float*)d_in[5];
    const float* W2         = (const float*)d_in[6];
    const float* root2      = (const float*)d_in[7];
    const float* b2         = (const float*)d_in[8];
    float*       out        = (float*)d_out;

    (void)in_sizes; (void)n_in; (void)out_size;

    zero_kernel<<<2048, 256>>>();                                        // 1
    count_kernel<<<(N_EDGES + 255) / 256, 256>>>(edge_index, edge_type); // 2 (+scan)
    scatter_kernel<<<(N_EDGES + SCAT_EPB - 1) / SCAT_EPB, 256>>>(edge_index); // 3
    msg1_kernel<<<dim3(N_REL, 6), 256>>>(x, W1);                         // 4 <- profiled
    root1_relu_kernel<<<(N_NODES * HID_C + 255) / 256, 256>>>(x, root1, b1); // 5
    root2_kernel<<<(N_NODES * OUT_C + 255) / 256, 256>>>(root2, b2, out);    // 6
    msg2_kernel<<<dim3(N_REL, 6), 512>>>(W2, out);                       // 7
}

// round 15
// speedup vs baseline: 1.1532x; 1.1532x over previous
#include <cuda_runtime.h>

#define N_NODES 50000
#define N_EDGES 1200000
#define N_REL   45
#define IN_C    64
#define HID_C   32
#define OUT_C   16

#define SCAT_EPB 2048   // edges per scatter block
#define XT_PAD   36     // xt/Wt row stride in floats (144B)
#define W2_PAD   20     // msg2 Wt row stride in floats (80B, 16B-aligned)

typedef unsigned long long u64;

#define RED2(ptr, v0, v1) \
    asm volatile("red.global.add.v2.f32 [%0], {%1, %2};" \
                 :: "l"(ptr), "f"(v0), "f"(v1) : "memory")
#define FMA2(acc, a, b) \
    asm("fma.rn.f32x2 %0, %1, %2, %0;" : "+l"(acc) : "l"(a), "l"(b))
#define PACK2(out, lo, hi) \
    asm("mov.b64 %0, {%1, %2};" : "=l"(out) : "f"(lo), "f"(hi))
#define UNPACK2(lo, hi, in) \
    asm("mov.b64 {%0, %1}, %2;" : "=f"(lo), "=f"(hi) : "l"(in))

// Scratch (device globals: no allocation allowed in kernel_launch)
__device__ int   g_cnt[N_REL * N_NODES];
__device__ int   g_hist[N_REL];
__device__ int   g_off[N_REL + 1];
__device__ int   g_cursor[N_REL];
__device__ unsigned g_done;
__device__ int   g_rel[N_EDGES];
__device__ int   gs_src[N_EDGES];
__device__ int   gs_dst[N_EDGES];
__device__ float gs_w[N_EDGES];
__device__ float g_h1[N_NODES * HID_C];
__device__ float g_hr[N_NODES * HID_C];

// ---------------------------------------------------------------------------
__global__ void zero_kernel() {
    int i = blockIdx.x * blockDim.x + threadIdx.x;
    int stride = gridDim.x * blockDim.x;
    for (; i < N_REL * N_NODES; i += stride) g_cnt[i] = 0;
    int j = blockIdx.x * blockDim.x + threadIdx.x;
    for (; j < N_NODES * HID_C; j += stride) g_h1[j] = 0.0f;
    if (blockIdx.x == 0 && threadIdx.x < N_REL) g_hist[threadIdx.x] = 0;
    if (blockIdx.x == 0 && threadIdx.x == 0) g_done = 0;
}

__global__ void count_kernel(const int* __restrict__ edge_index,
                             const int* __restrict__ edge_type) {
    __shared__ int sh[N_REL];
    if (threadIdx.x < N_REL) sh[threadIdx.x] = 0;
    __syncthreads();
    int e = blockIdx.x * blockDim.x + threadIdx.x;
    if (e < N_EDGES) {
        int dst = edge_index[N_EDGES + e];
        int rel = edge_type[e];
        g_rel[e] = rel;
        atomicAdd(&g_cnt[rel * N_NODES + dst], 1);
        atomicAdd(&sh[rel], 1);
    }
    __syncthreads();
    if (threadIdx.x < N_REL) {
        atomicAdd(&g_hist[threadIdx.x], sh[threadIdx.x]);
        __threadfence();
    }
    __syncthreads();
    if (threadIdx.x == 0) {
        unsigned t = atomicInc(&g_done, 0xffffffffu);
        if (t == gridDim.x - 1) {
            int acc = 0;
            for (int r = 0; r < N_REL; r++) {
                g_off[r] = acc;
                g_cursor[r] = acc;
                acc += g_hist[r];
            }
            g_off[N_REL] = acc;
        }
    }
}

__global__ __launch_bounds__(256)
void scatter_kernel(const int* __restrict__ edge_index) {
    __shared__ int sh_cnt[N_REL];
    __shared__ int sh_base[N_REL];
    const int blockStart = blockIdx.x * SCAT_EPB;

    if (threadIdx.x < N_REL) sh_cnt[threadIdx.x] = 0;
    __syncthreads();
    for (int i = threadIdx.x; i < SCAT_EPB; i += blockDim.x) {
        int e = blockStart + i;
        if (e < N_EDGES) atomicAdd(&sh_cnt[g_rel[e]], 1);
    }
    __syncthreads();
    if (threadIdx.x < N_REL) {
        sh_base[threadIdx.x] = atomicAdd(&g_cursor[threadIdx.x], sh_cnt[threadIdx.x]);
        sh_cnt[threadIdx.x] = 0;
    }
    __syncthreads();
    for (int i = threadIdx.x; i < SCAT_EPB; i += blockDim.x) {
        int e = blockStart + i;
        if (e >= N_EDGES) continue;
        int rel = g_rel[e];
        int pos = sh_base[rel] + atomicAdd(&sh_cnt[rel], 1);
        int src = edge_index[e];
        int dst = edge_index[N_EDGES + e];
        int c   = g_cnt[rel * N_NODES + dst];
        gs_src[pos] = src;
        gs_dst[pos] = dst;
        gs_w[pos]   = 1.0f / (float)(c > 0 ? c : 1);
    }
}

// ---------------------------------------------------------------------------
// Layer-1 messages: r13 form (best measured). Warp tile 32 edges x 32 ch;
// thread = 4 edges x 8 ch, f32x2 FMA, W pre-packed pairs from smem.
__global__ __launch_bounds__(256, 2)
void msg1_kernel(const float* __restrict__ x, const float* __restrict__ W1) {
    __shared__ float Wt[IN_C][XT_PAD];         // 9216B
    __shared__ float xt[8][32][XT_PAD];        // 36864B  (total 46080 < 48K)

    const int tid  = threadIdx.x;
    const int lane = tid & 31;
    const int warp = tid >> 5;     // 0..7
    const int r    = blockIdx.x;

    const float* Wr = W1 + r * IN_C * HID_C;
    for (int i = tid; i < IN_C * HID_C; i += 256)
        Wt[i >> 5][i & 31] = Wr[i];
    __syncthreads();

    const int segStart = g_off[r];
    const int segEnd   = g_off[r + 1];
    const int wg = blockIdx.y * 8 + warp;
    const int nw = gridDim.y * 8;

    const int eg   = (lane & 7) * 4;
    const int cg   = lane >> 3;
    const int part = lane & 1;

    for (int base = segStart + wg * 32; base < segEnd; base += nw * 32) {
        int n = segEnd - base; if (n > 32) n = 32;
        int s32 = 0, d32 = 0; float w32 = 0.0f;
        if (lane < n) {
            s32 = gs_src[base + lane];
            d32 = gs_dst[base + lane];
            w32 = gs_w[base + lane];
        } else {
            s32 = gs_src[segStart];
        }

        u64 accp[4][4];
#pragma unroll
        for (int i = 0; i < 4; i++)
#pragma unroll
            for (int p = 0; p < 4; p++) accp[i][p] = 0ull;

#pragma unroll
        for (int half = 0; half < 2; half++) {
#pragma unroll
            for (int pass = 0; pass < 2; pass++) {
                int row = (lane >> 1) + pass * 16;
                int s = __shfl_sync(0xffffffffu, s32, row);
                const float4* src4 = (const float4*)(x + (size_t)s * IN_C) + half * 8;
#pragma unroll
                for (int f = 0; f < 4; f++) {
                    float4 v = src4[part + 2 * f];
                    int kb = f * 8 + part * 4;
                    xt[warp][kb + 0][row] = v.x;
                    xt[warp][kb + 1][row] = v.y;
                    xt[warp][kb + 2][row] = v.z;
                    xt[warp][kb + 3][row] = v.w;
                }
            }
            __syncwarp();

#pragma unroll 8
            for (int kk = 0; kk < 32; kk++) {
                float4 xv = *(const float4*)&xt[warp][kk][eg];
                const ulonglong2* wrow =
                    (const ulonglong2*)&Wt[half * 32 + kk][cg * 8];
                ulonglong2 wA = wrow[0];
                ulonglong2 wB = wrow[1];
                u64 xx0, xx1, xx2, xx3;
                PACK2(xx0, xv.x, xv.x);
                PACK2(xx1, xv.y, xv.y);
                PACK2(xx2, xv.z, xv.z);
                PACK2(xx3, xv.w, xv.w);
                FMA2(accp[0][0], xx0, wA.x); FMA2(accp[0][1], xx0, wA.y);
                FMA2(accp[0][2], xx0, wB.x); FMA2(accp[0][3], xx0, wB.y);
                FMA2(accp[1][0], xx1, wA.x); FMA2(accp[1][1], xx1, wA.y);
                FMA2(accp[1][2], xx1, wB.x); FMA2(accp[1][3], xx1, wB.y);
                FMA2(accp[2][0], xx2, wA.x); FMA2(accp[2][1], xx2, wA.y);
                FMA2(accp[2][2], xx2, wB.x); FMA2(accp[2][3], xx2, wB.y);
                FMA2(accp[3][0], xx3, wA.x); FMA2(accp[3][1], xx3, wA.y);
                FMA2(accp[3][2], xx3, wB.x); FMA2(accp[3][3], xx3, wB.y);
            }
            __syncwarp();
        }

#pragma unroll
        for (int i = 0; i < 4; i++) {
            int e = eg + i;
            int d = __shfl_sync(0xffffffffu, d32, e);
            float we = __shfl_sync(0xffffffffu, w32, e);
            float* p = &g_h1[d * HID_C + cg * 8];
            float v0, v1;
            UNPACK2(v0, v1, accp[i][0]); RED2(p + 0, v0 * we, v1 * we);
            UNPACK2(v0, v1, accp[i][1]); RED2(p + 2, v0 * we, v1 * we);
            UNPACK2(v0, v1, accp[i][2]); RED2(p + 4, v0 * we, v1 * we);
            UNPACK2(v0, v1, accp[i][3]); RED2(p + 6, v0 * we, v1 * we);
        }
    }
}

// ---------------------------------------------------------------------------
__global__ void root1_relu_kernel(const float* __restrict__ x,
                                  const float* __restrict__ root,
                                  const float* __restrict__ b) {
    int t = blockIdx.x * blockDim.x + threadIdx.x;
    if (t >= N_NODES * HID_C) return;
    int n = t >> 5;
    int c = t & 31;
    float acc = b[c] + g_h1[t];
    const float4* xr = (const float4*)(x + n * IN_C);
#pragma unroll
    for (int i4 = 0; i4 < IN_C / 4; i4++) {
        float4 xv = xr[i4];
        acc += xv.x * root[(i4 * 4 + 0) * HID_C + c];
        acc += xv.y * root[(i4 * 4 + 1) * HID_C + c];
        acc += xv.z * root[(i4 * 4 + 2) * HID_C + c];
        acc += xv.w * root[(i4 * 4 + 3) * HID_C + c];
    }
    g_hr[t] = fmaxf(acc, 0.0f);
}

__global__ void root2_kernel(const float* __restrict__ root,
                             const float* __restrict__ b,
                             float* __restrict__ out) {
    int t = blockIdx.x * blockDim.x + threadIdx.x;
    if (t >= N_NODES * OUT_C) return;
    int n = t >> 4;
    int c = t & 15;
    float acc = b[c];
    const float4* hr = (const float4*)(g_hr + n * HID_C);
#pragma unroll
    for (int i4 = 0; i4 < HID_C / 4; i4++) {
        float4 hv = hr[i4];
        acc += hv.x * root[(i4 * 4 + 0) * OUT_C + c];
        acc += hv.y * root[(i4 * 4 + 1) * OUT_C + c];
        acc += hv.z * root[(i4 * 4 + 2) * OUT_C + c];
        acc += hv.w * root[(i4 * 4 + 3) * OUT_C + c];
    }
    out[t] = acc;
}

// ---------------------------------------------------------------------------
// Layer-2 messages: r13 recipe applied to (K=32, N=16). Warp tile = 32 edges
// x 16 channels; thread = 4 edges x 4 channels. g_hr staged transposed
// (distinct-data LDS), W2 pre-packed channel pairs, f32x2 FMA, RED2 scatter.
// Per kk per thread: 1 x-LDS + 1 W-LDS + 4 packs + 8 FMA2.
__global__ __launch_bounds__(256, 2)
void msg2_kernel(const float* __restrict__ W2, float* __restrict__ out) {
    __shared__ float Wt[HID_C][W2_PAD];        //  2560B
    __shared__ float ht[8][HID_C][XT_PAD];     // 36864B  (total 39424 < 48K)

    const int tid  = threadIdx.x;
    const int lane = tid & 31;
    const int warp = tid >> 5;     // 0..7
    const int r    = blockIdx.x;

    // stage W2_r: Wt[k][c] = W2[r][k][c]  (k<32, c<16)
    const float* Wr = W2 + r * HID_C * OUT_C;
    for (int i = tid; i < HID_C * OUT_C; i += 256)
        Wt[i >> 4][i & 15] = Wr[i];
    __syncthreads();

    const int segStart = g_off[r];
    const int segEnd   = g_off[r + 1];
    const int wg = blockIdx.y * 8 + warp;
    const int nw = gridDim.y * 8;

    const int eg   = (lane & 7) * 4;   // this thread's 4 edges
    const int cg   = lane >> 3;        // channel group (4 ch = 2 pairs)
    const int part = lane & 1;

    for (int base = segStart + wg * 32; base < segEnd; base += nw * 32) {
        int n = segEnd - base; if (n > 32) n = 32;
        int s32 = 0, d32 = 0; float w32 = 0.0f;
        if (lane < n) {
            s32 = gs_src[base + lane];
            d32 = gs_dst[base + lane];
            w32 = gs_w[base + lane];
        } else {
            s32 = gs_src[segStart];    // valid row, weight 0
        }

        u64 accp[4][2];
#pragma unroll
        for (int i = 0; i < 4; i++) { accp[i][0] = 0ull; accp[i][1] = 0ull; }

        // stage 32 rows x 32 k (transposed); 2 lanes per row, 4 float4 each
#pragma unroll
        for (int pass = 0; pass < 2; pass++) {
            int row = (lane >> 1) + pass * 16;
            int s = __shfl_sync(0xffffffffu, s32, row);
            const float4* src4 = (const float4*)(g_hr + (size_t)s * HID_C);
#pragma unroll
            for (int f = 0; f < 4; f++) {
                float4 v = src4[part + 2 * f];      // float4 idx 0..7
                int kb = (part + 2 * f) * 4;
                ht[warp][kb + 0][row] = v.x;
                ht[warp][kb + 1][row] = v.y;
                ht[warp][kb + 2][row] = v.z;
                ht[warp][kb + 3][row] = v.w;
            }
        }
        __syncwarp();

        // 32 k-steps
#pragma unroll 8
        for (int kk = 0; kk < HID_C; kk++) {
            float4 xv = *(const float4*)&ht[warp][kk][eg];
            ulonglong2 wp = *(const ulonglong2*)&Wt[kk][cg * 4];
            u64 xx0, xx1, xx2, xx3;
            PACK2(xx0, xv.x, xv.x);
            PACK2(xx1, xv.y, xv.y);
            PACK2(xx2, xv.z, xv.z);
            PACK2(xx3, xv.w, xv.w);
            FMA2(accp[0][0], xx0, wp.x); FMA2(accp[0][1], xx0, wp.y);
            FMA2(accp[1][0], xx1, wp.x); FMA2(accp[1][1], xx1, wp.y);
            FMA2(accp[2][0], xx2, wp.x); FMA2(accp[2][1], xx2, wp.y);
            FMA2(accp[3][0], xx3, wp.x); FMA2(accp[3][1], xx3, wp.y);
        }
        __syncwarp();

        // epilogue: unpack, scale, RED2 scatter (padded edges: w=0, d=0)
#pragma unroll
        for (int i = 0; i < 4; i++) {
            int e = eg + i;
            int d = __shfl_sync(0xffffffffu, d32, e);
            float we = __shfl_sync(0xffffffffu, w32, e);
            float* p = &out[d * OUT_C + cg * 4];
            float v0, v1;
            UNPACK2(v0, v1, accp[i][0]); RED2(p + 0, v0 * we, v1 * we);
            UNPACK2(v0, v1, accp[i][1]); RED2(p + 2, v0 * we, v1 * we);
        }
    }
}

// ---------------------------------------------------------------------------
extern "C" void kernel_launch(void* const* d_in, const int* in_sizes, int n_in,
                              void* d_out, int out_size) {
    const float* x          = (const float*)d_in[0];
    const int*   edge_index = (const int*)d_in[1];
    const int*   edge_type  = (const int*)d_in[2];
    const float* W1         = (const float*)d_in[3];
    const float* root1      = (const float*)d_in[4];
    const float* b1         = (const float*)d_in[5];
    const float* W2         = (const float*)d_in[6];
    const float* root2      = (const float*)d_in[7];
    const float* b2         = (const float*)d_in[8];
    float*       out        = (float*)d_out;

    (void)in_sizes; (void)n_in; (void)out_size;

    zero_kernel<<<2048, 256>>>();                                        // 1
    count_kernel<<<(N_EDGES + 255) / 256, 256>>>(edge_index, edge_type); // 2 (+scan)
    scatter_kernel<<<(N_EDGES + SCAT_EPB - 1) / SCAT_EPB, 256>>>(edge_index); // 3
    msg1_kernel<<<dim3(N_REL, 6), 256>>>(x, W1);                         // 4 <- profiled
    root1_relu_kernel<<<(N_NODES * HID_C + 255) / 256, 256>>>(x, root1, b1); // 5
    root2_kernel<<<(N_NODES * OUT_C + 255) / 256, 256>>>(root2, b2, out);    // 6
    msg2_kernel<<<dim3(N_REL, 6), 256>>>(W2, out);                       // 7
}

// round 16
// speedup vs baseline: 1.1811x; 1.0241x over previous
#include <cuda_runtime.h>

#define N_NODES 50000
#define N_EDGES 1200000
#define N_REL   45
#define IN_C    64
#define HID_C   32
#define OUT_C   16

#define SCAT_EPB 2048   // edges per scatter block
#define XT_PAD   36     // xt/Wt row stride in floats (144B)
#define W2_PAD   20     // msg2 Wt row stride in floats (80B, 16B-aligned)

typedef unsigned long long u64;

#define RED2(ptr, v0, v1) \
    asm volatile("red.global.add.v2.f32 [%0], {%1, %2};" \
                 :: "l"(ptr), "f"(v0), "f"(v1) : "memory")
#define FMA2(acc, a, b) \
    asm("fma.rn.f32x2 %0, %1, %2, %0;" : "+l"(acc) : "l"(a), "l"(b))
#define PACK2(out, lo, hi) \
    asm("mov.b64 %0, {%1, %2};" : "=l"(out) : "f"(lo), "f"(hi))
#define UNPACK2(lo, hi, in) \
    asm("mov.b64 {%0, %1}, %2;" : "=f"(lo), "=f"(hi) : "l"(in))

// Scratch (device globals: no allocation allowed in kernel_launch)
__device__ int   g_cnt[N_REL * N_NODES];   // per-(rel,dst) edge counts
__device__ int   g_hist[N_REL];
__device__ int   g_off[N_REL + 1];
__device__ int   g_cursor[N_REL];
__device__ unsigned g_done;
__device__ int2  gs_sd[N_EDGES];           // relation-sorted (src,dst)
__device__ float g_h1[N_NODES * HID_C];    // layer-1 message sums (zero-init)
__device__ float g_hr[N_NODES * HID_C];    // relu(msg + x@root1 + b1)

// ---------------------------------------------------------------------------
__global__ void zero_kernel() {
    int i = blockIdx.x * blockDim.x + threadIdx.x;
    int stride = gridDim.x * blockDim.x;
    for (; i < N_REL * N_NODES; i += stride) g_cnt[i] = 0;
    int j = blockIdx.x * blockDim.x + threadIdx.x;
    for (; j < N_NODES * HID_C; j += stride) g_h1[j] = 0.0f;
    if (blockIdx.x == 0 && threadIdx.x < N_REL) g_hist[threadIdx.x] = 0;
    if (blockIdx.x == 0 && threadIdx.x == 0) g_done = 0;
}

// counts per (rel,dst) + per-relation histogram; LAST block does the 45-bin
// exclusive scan (ticket pattern) so no separate scan launch is needed.
__global__ void count_kernel(const int* __restrict__ edge_index,
                             const int* __restrict__ edge_type) {
    __shared__ int sh[N_REL];
    if (threadIdx.x < N_REL) sh[threadIdx.x] = 0;
    __syncthreads();
    int e = blockIdx.x * blockDim.x + threadIdx.x;
    if (e < N_EDGES) {
        int dst = edge_index[N_EDGES + e];
        int rel = edge_type[e];
        atomicAdd(&g_cnt[rel * N_NODES + dst], 1);
        atomicAdd(&sh[rel], 1);
    }
    __syncthreads();
    if (threadIdx.x < N_REL) {
        atomicAdd(&g_hist[threadIdx.x], sh[threadIdx.x]);
        __threadfence();
    }
    __syncthreads();
    if (threadIdx.x == 0) {
        unsigned t = atomicInc(&g_done, 0xffffffffu);
        if (t == gridDim.x - 1) {
            int acc = 0;
            for (int r = 0; r < N_REL; r++) {
                g_off[r] = acc;
                g_cursor[r] = acc;
                acc += g_hist[r];
            }
            g_off[N_REL] = acc;
        }
    }
}

// Hierarchical-cursor relation sort. No per-edge g_cnt gather / weight store:
// msg kernels compute 1/cnt inline (one LDG+RCP per lane per 32-edge tile).
__global__ __launch_bounds__(256)
void scatter_kernel(const int* __restrict__ edge_index,
                    const int* __restrict__ edge_type) {
    __shared__ int sh_cnt[N_REL];
    __shared__ int sh_base[N_REL];
    const int blockStart = blockIdx.x * SCAT_EPB;

    if (threadIdx.x < N_REL) sh_cnt[threadIdx.x] = 0;
    __syncthreads();
    for (int i = threadIdx.x; i < SCAT_EPB; i += blockDim.x) {
        int e = blockStart + i;
        if (e < N_EDGES) atomicAdd(&sh_cnt[edge_type[e]], 1);
    }
    __syncthreads();
    if (threadIdx.x < N_REL) {
        sh_base[threadIdx.x] = atomicAdd(&g_cursor[threadIdx.x], sh_cnt[threadIdx.x]);
        sh_cnt[threadIdx.x] = 0;
    }
    __syncthreads();
    for (int i = threadIdx.x; i < SCAT_EPB; i += blockDim.x) {
        int e = blockStart + i;
        if (e >= N_EDGES) continue;
        int rel = edge_type[e];
        int pos = sh_base[rel] + atomicAdd(&sh_cnt[rel], 1);
        gs_sd[pos] = make_int2(edge_index[e], edge_index[N_EDGES + e]);
    }
}

// ---------------------------------------------------------------------------
// Layer-1 messages: r13 form (best measured). Warp tile 32 edges x 32 ch;
// thread = 4 edges x 8 ch, f32x2 FMA, W pre-packed pairs from smem.
// Edge weight 1/cnt computed inline from g_cnt.
__global__ __launch_bounds__(256, 2)
void msg1_kernel(const float* __restrict__ x, const float* __restrict__ W1) {
    __shared__ float Wt[IN_C][XT_PAD];         // 9216B
    __shared__ float xt[8][32][XT_PAD];        // 36864B  (total 46080 < 48K)

    const int tid  = threadIdx.x;
    const int lane = tid & 31;
    const int warp = tid >> 5;     // 0..7
    const int r    = blockIdx.x;

    const float* Wr = W1 + r * IN_C * HID_C;
    for (int i = tid; i < IN_C * HID_C; i += 256)
        Wt[i >> 5][i & 31] = Wr[i];
    __syncthreads();

    const int segStart = g_off[r];
    const int segEnd   = g_off[r + 1];
    const int wg = blockIdx.y * 8 + warp;
    const int nw = gridDim.y * 8;

    const int eg   = (lane & 7) * 4;
    const int cg   = lane >> 3;
    const int part = lane & 1;

    for (int base = segStart + wg * 32; base < segEnd; base += nw * 32) {
        int n = segEnd - base; if (n > 32) n = 32;
        int s32, d32 = 0; float w32 = 0.0f;
        if (lane < n) {
            int2 sd = gs_sd[base + lane];
            s32 = sd.x; d32 = sd.y;
            w32 = 1.0f / (float)g_cnt[r * N_NODES + sd.y];
        } else {
            s32 = gs_sd[segStart].x;   // valid row, weight 0 -> contributes 0
        }

        u64 accp[4][4];
#pragma unroll
        for (int i = 0; i < 4; i++)
#pragma unroll
            for (int p = 0; p < 4; p++) accp[i][p] = 0ull;

#pragma unroll
        for (int half = 0; half < 2; half++) {
#pragma unroll
            for (int pass = 0; pass < 2; pass++) {
                int row = (lane >> 1) + pass * 16;
                int s = __shfl_sync(0xffffffffu, s32, row);
                const float4* src4 = (const float4*)(x + (size_t)s * IN_C) + half * 8;
#pragma unroll
                for (int f = 0; f < 4; f++) {
                    float4 v = src4[part + 2 * f];
                    int kb = f * 8 + part * 4;
                    xt[warp][kb + 0][row] = v.x;
                    xt[warp][kb + 1][row] = v.y;
                    xt[warp][kb + 2][row] = v.z;
                    xt[warp][kb + 3][row] = v.w;
                }
            }
            __syncwarp();

#pragma unroll 8
            for (int kk = 0; kk < 32; kk++) {
                float4 xv = *(const float4*)&xt[warp][kk][eg];
                const ulonglong2* wrow =
                    (const ulonglong2*)&Wt[half * 32 + kk][cg * 8];
                ulonglong2 wA = wrow[0];
                ulonglong2 wB = wrow[1];
                u64 xx0, xx1, xx2, xx3;
                PACK2(xx0, xv.x, xv.x);
                PACK2(xx1, xv.y, xv.y);
                PACK2(xx2, xv.z, xv.z);
                PACK2(xx3, xv.w, xv.w);
                FMA2(accp[0][0], xx0, wA.x); FMA2(accp[0][1], xx0, wA.y);
                FMA2(accp[0][2], xx0, wB.x); FMA2(accp[0][3], xx0, wB.y);
                FMA2(accp[1][0], xx1, wA.x); FMA2(accp[1][1], xx1, wA.y);
                FMA2(accp[1][2], xx1, wB.x); FMA2(accp[1][3], xx1, wB.y);
                FMA2(accp[2][0], xx2, wA.x); FMA2(accp[2][1], xx2, wA.y);
                FMA2(accp[2][2], xx2, wB.x); FMA2(accp[2][3], xx2, wB.y);
                FMA2(accp[3][0], xx3, wA.x); FMA2(accp[3][1], xx3, wA.y);
                FMA2(accp[3][2], xx3, wB.x); FMA2(accp[3][3], xx3, wB.y);
            }
            __syncwarp();
        }

#pragma unroll
        for (int i = 0; i < 4; i++) {
            int e = eg + i;
            int d = __shfl_sync(0xffffffffu, d32, e);
            float we = __shfl_sync(0xffffffffu, w32, e);
            float* p = &g_h1[d * HID_C + cg * 8];
            float v0, v1;
            UNPACK2(v0, v1, accp[i][0]); RED2(p + 0, v0 * we, v1 * we);
            UNPACK2(v0, v1, accp[i][1]); RED2(p + 2, v0 * we, v1 * we);
            UNPACK2(v0, v1, accp[i][2]); RED2(p + 4, v0 * we, v1 * we);
            UNPACK2(v0, v1, accp[i][3]); RED2(p + 6, v0 * we, v1 * we);
        }
    }
}

// ---------------------------------------------------------------------------
__global__ void root1_relu_kernel(const float* __restrict__ x,
                                  const float* __restrict__ root,
                                  const float* __restrict__ b) {
    int t = blockIdx.x * blockDim.x + threadIdx.x;
    if (t >= N_NODES * HID_C) return;
    int n = t >> 5;
    int c = t & 31;
    float acc = b[c] + g_h1[t];
    const float4* xr = (const float4*)(x + n * IN_C);
#pragma unroll
    for (int i4 = 0; i4 < IN_C / 4; i4++) {
        float4 xv = xr[i4];
        acc += xv.x * root[(i4 * 4 + 0) * HID_C + c];
        acc += xv.y * root[(i4 * 4 + 1) * HID_C + c];
        acc += xv.z * root[(i4 * 4 + 2) * HID_C + c];
        acc += xv.w * root[(i4 * 4 + 3) * HID_C + c];
    }
    g_hr[t] = fmaxf(acc, 0.0f);
}

__global__ void root2_kernel(const float* __restrict__ root,
                             const float* __restrict__ b,
                             float* __restrict__ out) {
    int t = blockIdx.x * blockDim.x + threadIdx.x;
    if (t >= N_NODES * OUT_C) return;
    int n = t >> 4;
    int c = t & 15;
    float acc = b[c];
    const float4* hr = (const float4*)(g_hr + n * HID_C);
#pragma unroll
    for (int i4 = 0; i4 < HID_C / 4; i4++) {
        float4 hv = hr[i4];
        acc += hv.x * root[(i4 * 4 + 0) * OUT_C + c];
        acc += hv.y * root[(i4 * 4 + 1) * OUT_C + c];
        acc += hv.z * root[(i4 * 4 + 2) * OUT_C + c];
        acc += hv.w * root[(i4 * 4 + 3) * OUT_C + c];
    }
    out[t] = acc;
}

// ---------------------------------------------------------------------------
// Layer-2 messages: warp tile 32 edges x 16 ch; thread = 4 edges x 4 ch,
// f32x2 FMA, transposed smem staging, RED2 scatter. Weight inline from g_cnt.
__global__ __launch_bounds__(256, 2)
void msg2_kernel(const float* __restrict__ W2, float* __restrict__ out) {
    __shared__ float Wt[HID_C][W2_PAD];        //  2560B
    __shared__ float ht[8][HID_C][XT_PAD];     // 36864B  (total 39424 < 48K)

    const int tid  = threadIdx.x;
    const int lane = tid & 31;
    const int warp = tid >> 5;     // 0..7
    const int r    = blockIdx.x;

    const float* Wr = W2 + r * HID_C * OUT_C;
    for (int i = tid; i < HID_C * OUT_C; i += 256)
        Wt[i >> 4][i & 15] = Wr[i];
    __syncthreads();

    const int segStart = g_off[r];
    const int segEnd   = g_off[r + 1];
    const int wg = blockIdx.y * 8 + warp;
    const int nw = gridDim.y * 8;

    const int eg   = (lane & 7) * 4;
    const int cg   = lane >> 3;
    const int part = lane & 1;

    for (int base = segStart + wg * 32; base < segEnd; base += nw * 32) {
        int n = segEnd - base; if (n > 32) n = 32;
        int s32, d32 = 0; float w32 = 0.0f;
        if (lane < n) {
            int2 sd = gs_sd[base + lane];
            s32 = sd.x; d32 = sd.y;
            w32 = 1.0f / (float)g_cnt[r * N_NODES + sd.y];
        } else {
            s32 = gs_sd[segStart].x;
        }

        u64 accp[4][2];
#pragma unroll
        for (int i = 0; i < 4; i++) { accp[i][0] = 0ull; accp[i][1] = 0ull; }

#pragma unroll
        for (int pass = 0; pass < 2; pass++) {
            int row = (lane >> 1) + pass * 16;
            int s = __shfl_sync(0xffffffffu, s32, row);
            const float4* src4 = (const float4*)(g_hr + (size_t)s * HID_C);
#pragma unroll
            for (int f = 0; f < 4; f++) {
                float4 v = src4[part + 2 * f];
                int kb = (part + 2 * f) * 4;
                ht[warp][kb + 0][row] = v.x;
                ht[warp][kb + 1][row] = v.y;
                ht[warp][kb + 2][row] = v.z;
                ht[warp][kb + 3][row] = v.w;
            }
        }
        __syncwarp();

#pragma unroll 8
        for (int kk = 0; kk < HID_C; kk++) {
            float4 xv = *(const float4*)&ht[warp][kk][eg];
            ulonglong2 wp = *(const ulonglong2*)&Wt[kk][cg * 4];
            u64 xx0, xx1, xx2, xx3;
            PACK2(xx0, xv.x, xv.x);
            PACK2(xx1, xv.y, xv.y);
            PACK2(xx2, xv.z, xv.z);
            PACK2(xx3, xv.w, xv.w);
            FMA2(accp[0][0], xx0, wp.x); FMA2(accp[0][1], xx0, wp.y);
            FMA2(accp[1][0], xx1, wp.x); FMA2(accp[1][1], xx1, wp.y);
            FMA2(accp[2][0], xx2, wp.x); FMA2(accp[2][1], xx2, wp.y);
            FMA2(accp[3][0], xx3, wp.x); FMA2(accp[3][1], xx3, wp.y);
        }
        __syncwarp();

#pragma unroll
        for (int i = 0; i < 4; i++) {
            int e = eg + i;
            int d = __shfl_sync(0xffffffffu, d32, e);
            float we = __shfl_sync(0xffffffffu, w32, e);
            float* p = &out[d * OUT_C + cg * 4];
            float v0, v1;
            UNPACK2(v0, v1, accp[i][0]); RED2(p + 0, v0 * we, v1 * we);
            UNPACK2(v0, v1, accp[i][1]); RED2(p + 2, v0 * we, v1 * we);
        }
    }
}

// ---------------------------------------------------------------------------
extern "C" void kernel_launch(void* const* d_in, const int* in_sizes, int n_in,
                              void* d_out, int out_size) {
    const float* x          = (const float*)d_in[0];
    const int*   edge_index = (const int*)d_in[1];
    const int*   edge_type  = (const int*)d_in[2];
    const float* W1         = (const float*)d_in[3];
    const float* root1      = (const float*)d_in[4];
    const float* b1         = (const float*)d_in[5];
    const float* W2         = (const float*)d_in[6];
    const float* root2      = (const float*)d_in[7];
    const float* b2         = (const float*)d_in[8];
    float*       out        = (float*)d_out;

    (void)in_sizes; (void)n_in; (void)out_size;

    zero_kernel<<<2048, 256>>>();                                        // 1
    count_kernel<<<(N_EDGES + 255) / 256, 256>>>(edge_index, edge_type); // 2 (+scan)
    scatter_kernel<<<(N_EDGES + SCAT_EPB - 1) / SCAT_EPB, 256>>>(
        edge_index, edge_type);                                          // 3
    msg1_kernel<<<dim3(N_REL, 6), 256>>>(x, W1);                         // 4 <- profiled
    root1_relu_kernel<<<(N_NODES * HID_C + 255) / 256, 256>>>(x, root1, b1); // 5
    root2_kernel<<<(N_NODES * OUT_C + 255) / 256, 256>>>(root2, b2, out);    // 6
    msg2_kernel<<<dim3(N_REL, 6), 256>>>(W2, out);                       // 7
}

// round 17
// speedup vs baseline: 1.1876x; 1.0055x over previous
#include <cuda_runtime.h>

#define N_NODES 50000
#define N_EDGES 1200000
#define N_REL   45
#define IN_C    64
#define HID_C   32
#define OUT_C   16

#define SCAT_EPB 2048   // edges per scatter block
#define XT_PAD   36     // xt/Wt row stride in floats (144B)
#define W2_PAD   20     // msg2 Wt row stride in floats (80B, 16B-aligned)

typedef unsigned long long u64;

#define RED2(ptr, v0, v1) \
    asm volatile("red.global.add.v2.f32 [%0], {%1, %2};" \
                 :: "l"(ptr), "f"(v0), "f"(v1) : "memory")
#define FMA2(acc, a, b) \
    asm("fma.rn.f32x2 %0, %1, %2, %0;" : "+l"(acc) : "l"(a), "l"(b))
#define PACK2(out, lo, hi) \
    asm("mov.b64 %0, {%1, %2};" : "=l"(out) : "f"(lo), "f"(hi))
#define UNPACK2(lo, hi, in) \
    asm("mov.b64 {%0, %1}, %2;" : "=f"(lo), "=f"(hi) : "l"(in))

// Scratch (device globals: no allocation allowed in kernel_launch)
__device__ int   g_cnt[N_REL * N_NODES];   // per-(rel,dst) edge counts
__device__ int   g_hist[N_REL];
__device__ int   g_off[N_REL + 1];
__device__ int   g_cursor[N_REL];
__device__ unsigned g_done;
__device__ int2  gs_sd[N_EDGES];           // relation-sorted (src,dst)
__device__ float g_h1[N_NODES * HID_C];    // layer-1 message sums (zero-init)
__device__ float g_hr[N_NODES * HID_C];    // relu(msg + x@root1 + b1)

// ---------------------------------------------------------------------------
__global__ void zero_kernel() {
    int i = blockIdx.x * blockDim.x + threadIdx.x;
    int stride = gridDim.x * blockDim.x;
    for (; i < N_REL * N_NODES; i += stride) g_cnt[i] = 0;
    int j = blockIdx.x * blockDim.x + threadIdx.x;
    for (; j < N_NODES * HID_C; j += stride) g_h1[j] = 0.0f;
    if (blockIdx.x == 0 && threadIdx.x < N_REL) g_hist[threadIdx.x] = 0;
    if (blockIdx.x == 0 && threadIdx.x == 0) g_done = 0;
}

// counts per (rel,dst) + per-relation histogram; LAST block does the 45-bin
// exclusive scan (ticket pattern) so no separate scan launch is needed.
__global__ void count_kernel(const int* __restrict__ edge_index,
                             const int* __restrict__ edge_type) {
    __shared__ int sh[N_REL];
    if (threadIdx.x < N_REL) sh[threadIdx.x] = 0;
    __syncthreads();
    int e = blockIdx.x * blockDim.x + threadIdx.x;
    if (e < N_EDGES) {
        int dst = edge_index[N_EDGES + e];
        int rel = edge_type[e];
        atomicAdd(&g_cnt[rel * N_NODES + dst], 1);
        atomicAdd(&sh[rel], 1);
    }
    __syncthreads();
    if (threadIdx.x < N_REL) {
        atomicAdd(&g_hist[threadIdx.x], sh[threadIdx.x]);
        __threadfence();
    }
    __syncthreads();
    if (threadIdx.x == 0) {
        unsigned t = atomicInc(&g_done, 0xffffffffu);
        if (t == gridDim.x - 1) {
            int acc = 0;
            for (int r = 0; r < N_REL; r++) {
                g_off[r] = acc;
                g_cursor[r] = acc;
                acc += g_hist[r];
            }
            g_off[N_REL] = acc;
        }
    }
}

// Hierarchical-cursor relation sort. Weight 1/cnt computed inline downstream.
__global__ __launch_bounds__(256)
void scatter_kernel(const int* __restrict__ edge_index,
                    const int* __restrict__ edge_type) {
    __shared__ int sh_cnt[N_REL];
    __shared__ int sh_base[N_REL];
    const int blockStart = blockIdx.x * SCAT_EPB;

    if (threadIdx.x < N_REL) sh_cnt[threadIdx.x] = 0;
    __syncthreads();
    for (int i = threadIdx.x; i < SCAT_EPB; i += blockDim.x) {
        int e = blockStart + i;
        if (e < N_EDGES) atomicAdd(&sh_cnt[edge_type[e]], 1);
    }
    __syncthreads();
    if (threadIdx.x < N_REL) {
        sh_base[threadIdx.x] = atomicAdd(&g_cursor[threadIdx.x], sh_cnt[threadIdx.x]);
        sh_cnt[threadIdx.x] = 0;
    }
    __syncthreads();
    for (int i = threadIdx.x; i < SCAT_EPB; i += blockDim.x) {
        int e = blockStart + i;
        if (e >= N_EDGES) continue;
        int rel = edge_type[e];
        int pos = sh_base[rel] + atomicAdd(&sh_cnt[rel], 1);
        gs_sd[pos] = make_int2(edge_index[e], edge_index[N_EDGES + e]);
    }
}

// ---------------------------------------------------------------------------
// Layer-1 messages: warp tile 32 edges x 32 ch; thread = 4 edges x 8 ch,
// f32x2 FMA, W pre-packed pairs from smem. 3 blocks/SM (24 warps) for
// latency hiding; grid (45,9)=405 blocks = single wave at 3/SM.
__global__ __launch_bounds__(256, 3)
void msg1_kernel(const float* __restrict__ x, const float* __restrict__ W1) {
    __shared__ float Wt[IN_C][XT_PAD];         // 9216B
    __shared__ float xt[8][32][XT_PAD];        // 36864B  (46KB x3 = 138KB/SM)

    const int tid  = threadIdx.x;
    const int lane = tid & 31;
    const int warp = tid >> 5;     // 0..7
    const int r    = blockIdx.x;

    const float* Wr = W1 + r * IN_C * HID_C;
    for (int i = tid; i < IN_C * HID_C; i += 256)
        Wt[i >> 5][i & 31] = Wr[i];
    __syncthreads();

    const int segStart = g_off[r];
    const int segEnd   = g_off[r + 1];
    const int wg = blockIdx.y * 8 + warp;
    const int nw = gridDim.y * 8;

    const int eg   = (lane & 7) * 4;
    const int cg   = lane >> 3;
    const int part = lane & 1;

    for (int base = segStart + wg * 32; base < segEnd; base += nw * 32) {
        int n = segEnd - base; if (n > 32) n = 32;
        int s32, d32 = 0; float w32 = 0.0f;
        if (lane < n) {
            int2 sd = gs_sd[base + lane];
            s32 = sd.x; d32 = sd.y;
            w32 = 1.0f / (float)g_cnt[r * N_NODES + sd.y];
        } else {
            s32 = gs_sd[segStart].x;   // valid row, weight 0 -> contributes 0
        }

        u64 accp[4][4];
#pragma unroll
        for (int i = 0; i < 4; i++)
#pragma unroll
            for (int p = 0; p < 4; p++) accp[i][p] = 0ull;

#pragma unroll
        for (int half = 0; half < 2; half++) {
#pragma unroll
            for (int pass = 0; pass < 2; pass++) {
                int row = (lane >> 1) + pass * 16;
                int s = __shfl_sync(0xffffffffu, s32, row);
                const float4* src4 = (const float4*)(x + (size_t)s * IN_C) + half * 8;
#pragma unroll
                for (int f = 0; f < 4; f++) {
                    float4 v = src4[part + 2 * f];
                    int kb = f * 8 + part * 4;
                    xt[warp][kb + 0][row] = v.x;
                    xt[warp][kb + 1][row] = v.y;
                    xt[warp][kb + 2][row] = v.z;
                    xt[warp][kb + 3][row] = v.w;
                }
            }
            __syncwarp();

#pragma unroll 8
            for (int kk = 0; kk < 32; kk++) {
                float4 xv = *(const float4*)&xt[warp][kk][eg];
                const ulonglong2* wrow =
                    (const ulonglong2*)&Wt[half * 32 + kk][cg * 8];
                ulonglong2 wA = wrow[0];
                ulonglong2 wB = wrow[1];
                u64 xx0, xx1, xx2, xx3;
                PACK2(xx0, xv.x, xv.x);
                PACK2(xx1, xv.y, xv.y);
                PACK2(xx2, xv.z, xv.z);
                PACK2(xx3, xv.w, xv.w);
                FMA2(accp[0][0], xx0, wA.x); FMA2(accp[0][1], xx0, wA.y);
                FMA2(accp[0][2], xx0, wB.x); FMA2(accp[0][3], xx0, wB.y);
                FMA2(accp[1][0], xx1, wA.x); FMA2(accp[1][1], xx1, wA.y);
                FMA2(accp[1][2], xx1, wB.x); FMA2(accp[1][3], xx1, wB.y);
                FMA2(accp[2][0], xx2, wA.x); FMA2(accp[2][1], xx2, wA.y);
                FMA2(accp[2][2], xx2, wB.x); FMA2(accp[2][3], xx2, wB.y);
                FMA2(accp[3][0], xx3, wA.x); FMA2(accp[3][1], xx3, wA.y);
                FMA2(accp[3][2], xx3, wB.x); FMA2(accp[3][3], xx3, wB.y);
            }
            __syncwarp();
        }

#pragma unroll
        for (int i = 0; i < 4; i++) {
            int e = eg + i;
            int d = __shfl_sync(0xffffffffu, d32, e);
            float we = __shfl_sync(0xffffffffu, w32, e);
            float* p = &g_h1[d * HID_C + cg * 8];
            float v0, v1;
            UNPACK2(v0, v1, accp[i][0]); RED2(p + 0, v0 * we, v1 * we);
            UNPACK2(v0, v1, accp[i][1]); RED2(p + 2, v0 * we, v1 * we);
            UNPACK2(v0, v1, accp[i][2]); RED2(p + 4, v0 * we, v1 * we);
            UNPACK2(v0, v1, accp[i][3]); RED2(p + 6, v0 * we, v1 * we);
        }
    }
}

// ---------------------------------------------------------------------------
__global__ void root1_relu_kernel(const float* __restrict__ x,
                                  const float* __restrict__ root,
                                  const float* __restrict__ b) {
    int t = blockIdx.x * blockDim.x + threadIdx.x;
    if (t >= N_NODES * HID_C) return;
    int n = t >> 5;
    int c = t & 31;
    float acc = b[c] + g_h1[t];
    const float4* xr = (const float4*)(x + n * IN_C);
#pragma unroll
    for (int i4 = 0; i4 < IN_C / 4; i4++) {
        float4 xv = xr[i4];
        acc += xv.x * root[(i4 * 4 + 0) * HID_C + c];
        acc += xv.y * root[(i4 * 4 + 1) * HID_C + c];
        acc += xv.z * root[(i4 * 4 + 2) * HID_C + c];
        acc += xv.w * root[(i4 * 4 + 3) * HID_C + c];
    }
    g_hr[t] = fmaxf(acc, 0.0f);
}

__global__ void root2_kernel(const float* __restrict__ root,
                             const float* __restrict__ b,
                             float* __restrict__ out) {
    int t = blockIdx.x * blockDim.x + threadIdx.x;
    if (t >= N_NODES * OUT_C) return;
    int n = t >> 4;
    int c = t & 15;
    float acc = b[c];
    const float4* hr = (const float4*)(g_hr + n * HID_C);
#pragma unroll
    for (int i4 = 0; i4 < HID_C / 4; i4++) {
        float4 hv = hr[i4];
        acc += hv.x * root[(i4 * 4 + 0) * OUT_C + c];
        acc += hv.y * root[(i4 * 4 + 1) * OUT_C + c];
        acc += hv.z * root[(i4 * 4 + 2) * OUT_C + c];
        acc += hv.w * root[(i4 * 4 + 3) * OUT_C + c];
    }
    out[t] = acc;
}

// ---------------------------------------------------------------------------
// Layer-2 messages: warp tile 32 edges x 16 ch; thread = 4 edges x 4 ch,
// f32x2 FMA, transposed smem staging, RED2 scatter. 3 blocks/SM.
__global__ __launch_bounds__(256, 3)
void msg2_kernel(const float* __restrict__ W2, float* __restrict__ out) {
    __shared__ float Wt[HID_C][W2_PAD];        //  2560B
    __shared__ float ht[8][HID_C][XT_PAD];     // 36864B

    const int tid  = threadIdx.x;
    const int lane = tid & 31;
    const int warp = tid >> 5;     // 0..7
    const int r    = blockIdx.x;

    const float* Wr = W2 + r * HID_C * OUT_C;
    for (int i = tid; i < HID_C * OUT_C; i += 256)
        Wt[i >> 4][i & 15] = Wr[i];
    __syncthreads();

    const int segStart = g_off[r];
    const int segEnd   = g_off[r + 1];
    const int wg = blockIdx.y * 8 + warp;
    const int nw = gridDim.y * 8;

    const int eg   = (lane & 7) * 4;
    const int cg   = lane >> 3;
    const int part = lane & 1;

    for (int base = segStart + wg * 32; base < segEnd; base += nw * 32) {
        int n = segEnd - base; if (n > 32) n = 32;
        int s32, d32 = 0; float w32 = 0.0f;
        if (lane < n) {
            int2 sd = gs_sd[base + lane];
            s32 = sd.x; d32 = sd.y;
            w32 = 1.0f / (float)g_cnt[r * N_NODES + sd.y];
        } else {
            s32 = gs_sd[segStart].x;
        }

        u64 accp[4][2];
#pragma unroll
        for (int i = 0; i < 4; i++) { accp[i][0] = 0ull; accp[i][1] = 0ull; }

#pragma unroll
        for (int pass = 0; pass < 2; pass++) {
            int row = (lane >> 1) + pass * 16;
            int s = __shfl_sync(0xffffffffu, s32, row);
            const float4* src4 = (const float4*)(g_hr + (size_t)s * HID_C);
#pragma unroll
            for (int f = 0; f < 4; f++) {
                float4 v = src4[part + 2 * f];
                int kb = (part + 2 * f) * 4;
                ht[warp][kb + 0][row] = v.x;
                ht[warp][kb + 1][row] = v.y;
                ht[warp][kb + 2][row] = v.z;
                ht[warp][kb + 3][row] = v.w;
            }
        }
        __syncwarp();

#pragma unroll 8
        for (int kk = 0; kk < HID_C; kk++) {
            float4 xv = *(const float4*)&ht[warp][kk][eg];
            ulonglong2 wp = *(const ulonglong2*)&Wt[kk][cg * 4];
            u64 xx0, xx1, xx2, xx3;
            PACK2(xx0, xv.x, xv.x);
            PACK2(xx1, xv.y, xv.y);
            PACK2(xx2, xv.z, xv.z);
            PACK2(xx3, xv.w, xv.w);
            FMA2(accp[0][0], xx0, wp.x); FMA2(accp[0][1], xx0, wp.y);
            FMA2(accp[1][0], xx1, wp.x); FMA2(accp[1][1], xx1, wp.y);
            FMA2(accp[2][0], xx2, wp.x); FMA2(accp[2][1], xx2, wp.y);
            FMA2(accp[3][0], xx3, wp.x); FMA2(accp[3][1], xx3, wp.y);
        }
        __syncwarp();

#pragma unroll
        for (int i = 0; i < 4; i++) {
            int e = eg + i;
            int d = __shfl_sync(0xffffffffu, d32, e);
            float we = __shfl_sync(0xffffffffu, w32, e);
            float* p = &out[d * OUT_C + cg * 4];
            float v0, v1;
            UNPACK2(v0, v1, accp[i][0]); RED2(p + 0, v0 * we, v1 * we);
            UNPACK2(v0, v1, accp[i][1]); RED2(p + 2, v0 * we, v1 * we);
        }
    }
}

// ---------------------------------------------------------------------------
extern "C" void kernel_launch(void* const* d_in, const int* in_sizes, int n_in,
                              void* d_out, int out_size) {
    const float* x          = (const float*)d_in[0];
    const int*   edge_index = (const int*)d_in[1];
    const int*   edge_type  = (const int*)d_in[2];
    const float* W1         = (const float*)d_in[3];
    const float* root1      = (const float*)d_in[4];
    const float* b1         = (const float*)d_in[5];
    const float* W2         = (const float*)d_in[6];
    const float* root2      = (const float*)d_in[7];
    const float* b2         = (const float*)d_in[8];
    float*       out        = (float*)d_out;

    (void)in_sizes; (void)n_in; (void)out_size;

    zero_kernel<<<2048, 256>>>();                                        // 1
    count_kernel<<<(N_EDGES + 255) / 256, 256>>>(edge_index, edge_type); // 2 (+scan)
    scatter_kernel<<<(N_EDGES + SCAT_EPB - 1) / SCAT_EPB, 256>>>(
        edge_index, edge_type);                                          // 3
    msg1_kernel<<<dim3(N_REL, 9), 256>>>(x, W1);                         // 4 <- profiled
    root1_relu_kernel<<<(N_NODES * HID_C + 255) / 256, 256>>>(x, root1, b1); // 5
    root2_kernel<<<(N_NODES * OUT_C + 255) / 256, 256>>>(root2, b2, out);    // 6
    msg2_kernel<<<dim3(N_REL, 9), 256>>>(W2, out);                       // 7
}